// round 1
// baseline (speedup 1.0000x reference)
#include <cuda_runtime.h>

// Problem constants
// B=4, C=256, H=W=80, N=6400, heads=8 total -> per-dilation 4 heads of hd=32
#define NPIX   6400
#define SCALE  0.17677669529663687f   // 32^-0.5

// Scratch (device globals: allocation-free per harness rules)
__device__ float g_qkv [4 * 768 * 6400];   // [b, o, n], o = s*256 + dil*128 + head*32 + hd
__device__ float g_attn[4 * 256 * 6400];   // [b, ch, n] channel-major, ch = dil*128 + head*32 + hd

// ---------------------------------------------------------------------------
// Kernel A: qkv[b,o,n] = sum_c w_qkv[o,c] * y[b,c,n]   (y = concat(rgb, ir))
// Tiled fp32 GEMM: 128x128x16, 256 threads, 8x8 micro-tile.
// ---------------------------------------------------------------------------
__global__ __launch_bounds__(256) void qkv_gemm(const float* __restrict__ rgb,
                                                const float* __restrict__ ir,
                                                const float* __restrict__ w)
{
    __shared__ float As[16][128];   // As[k][m] = w[m0+m, k0+k]
    __shared__ float Bs[16][128];   // Bs[k][n] = y[b, k0+k, n0+n]

    const int b  = blockIdx.z;
    const int n0 = blockIdx.x * 128;
    const int m0 = blockIdx.y * 128;
    const int tid = threadIdx.x;
    const int tm = (tid >> 4) * 8;
    const int tn = (tid & 15) * 8;

    const float* rb = rgb + (size_t)b * 128 * NPIX;
    const float* ib = ir  + (size_t)b * 128 * NPIX;

    float acc[8][8];
    #pragma unroll
    for (int i = 0; i < 8; i++)
        #pragma unroll
        for (int j = 0; j < 8; j++) acc[i][j] = 0.f;

    for (int k0 = 0; k0 < 256; k0 += 16) {
        // Load A tile: 128(m) x 16(k); w row-major [o, c]
        #pragma unroll
        for (int t = 0; t < 2; t++) {
            int idx = tid * 2 + t;
            int row = idx >> 2;
            int col = (idx & 3) * 4;
            float4 v = *(const float4*)(w + (size_t)(m0 + row) * 256 + k0 + col);
            As[col + 0][row] = v.x;
            As[col + 1][row] = v.y;
            As[col + 2][row] = v.z;
            As[col + 3][row] = v.w;
        }
        // Load B tile: 16(k) x 128(n); y channel-major, contiguous in n
        #pragma unroll
        for (int t = 0; t < 2; t++) {
            int idx = tid * 2 + t;
            int kr = idx >> 5;
            int nc = (idx & 31) * 4;
            int c = k0 + kr;
            const float* src = (c < 128) ? (rb + (size_t)c * NPIX + n0 + nc)
                                         : (ib + (size_t)(c - 128) * NPIX + n0 + nc);
            *(float4*)&Bs[kr][nc] = *(const float4*)src;
        }
        __syncthreads();

        #pragma unroll
        for (int kk = 0; kk < 16; kk++) {
            float4 a0 = *(const float4*)&As[kk][tm];
            float4 a1 = *(const float4*)&As[kk][tm + 4];
            float4 b0 = *(const float4*)&Bs[kk][tn];
            float4 b1 = *(const float4*)&Bs[kk][tn + 4];
            float a[8] = {a0.x, a0.y, a0.z, a0.w, a1.x, a1.y, a1.z, a1.w};
            float bb[8] = {b0.x, b0.y, b0.z, b0.w, b1.x, b1.y, b1.z, b1.w};
            #pragma unroll
            for (int i = 0; i < 8; i++)
                #pragma unroll
                for (int j = 0; j < 8; j++)
                    acc[i][j] = fmaf(a[i], bb[j], acc[i][j]);
        }
        __syncthreads();
    }

    float* outb = g_qkv + (size_t)b * 768 * NPIX;
    #pragma unroll
    for (int i = 0; i < 8; i++) {
        float* dst = outb + (size_t)(m0 + tm + i) * NPIX + n0 + tn;
        *(float4*)(dst)     = make_float4(acc[i][0], acc[i][1], acc[i][2], acc[i][3]);
        *(float4*)(dst + 4) = make_float4(acc[i][4], acc[i][5], acc[i][6], acc[i][7]);
    }
}

// ---------------------------------------------------------------------------
// Kernel B: dilated local attention. One thread per (b, dil, head, pixel).
// Zero-padded OOB neighbors produce exact logit 0 (matching jnp.pad + unfold).
// ---------------------------------------------------------------------------
__global__ __launch_bounds__(256) void attn_kernel()
{
    const int n    = blockIdx.x * 256 + threadIdx.x;   // pixel index, < 6400
    const int dh   = blockIdx.y;                       // dil*4 + head
    const int dil  = dh >> 2;
    const int head = dh & 3;
    const int b    = blockIdx.z;
    const int d    = dil ? 3 : 2;                      // dilation 2 or 3

    const int r = n / 80;
    const int c = n % 80;

    const float* qb = g_qkv + ((size_t)(b * 768 + dil * 128 + head * 32)) * NPIX + n;
    const float* kb = qb + (size_t)256 * NPIX;
    const float* vb = qb + (size_t)512 * NPIX;

    float q[32];
    #pragma unroll
    for (int hd = 0; hd < 32; hd++) q[hd] = qb[hd * NPIX];

    float sc[9];
    #pragma unroll
    for (int jj = 0; jj < 9; jj++) {
        int di = jj / 3 - 1;
        int dj = jj % 3 - 1;
        int rr = r + di * d;
        int cc = c + dj * d;
        float s = 0.f;
        if (rr >= 0 && rr < 80 && cc >= 0 && cc < 80) {
            int off = di * d * 80 + dj * d;
            #pragma unroll
            for (int hd = 0; hd < 32; hd++)
                s = fmaf(q[hd], kb[hd * NPIX + off], s);
        }
        sc[jj] = s * SCALE;
    }

    float m = sc[0];
    #pragma unroll
    for (int jj = 1; jj < 9; jj++) m = fmaxf(m, sc[jj]);
    float sum = 0.f;
    #pragma unroll
    for (int jj = 0; jj < 9; jj++) { sc[jj] = __expf(sc[jj] - m); sum += sc[jj]; }
    const float inv = 1.f / sum;

    float out[32];
    #pragma unroll
    for (int hd = 0; hd < 32; hd++) out[hd] = 0.f;

    #pragma unroll
    for (int jj = 0; jj < 9; jj++) {
        int di = jj / 3 - 1;
        int dj = jj % 3 - 1;
        int rr = r + di * d;
        int cc = c + dj * d;
        if (rr >= 0 && rr < 80 && cc >= 0 && cc < 80) {
            int off = di * d * 80 + dj * d;
            float p = sc[jj] * inv;
            #pragma unroll
            for (int hd = 0; hd < 32; hd++)
                out[hd] = fmaf(p, vb[hd * NPIX + off], out[hd]);
        }
    }

    float* ob = g_attn + ((size_t)(b * 256 + dil * 128 + head * 32)) * NPIX + n;
    #pragma unroll
    for (int hd = 0; hd < 32; hd++) ob[hd * NPIX] = out[hd];
}

// ---------------------------------------------------------------------------
// Kernel C: out[b,n,o] = sum_c attn[b,c,n]*w_proj[o,c] + b_proj[o] + y[b,o,n]
// Same tiled GEMM; M dim = o (256 -> 2 tiles), N dim = pixels.
// ---------------------------------------------------------------------------
__global__ __launch_bounds__(256) void proj_kernel(const float* __restrict__ w,
                                                   const float* __restrict__ bias,
                                                   const float* __restrict__ rgb,
                                                   const float* __restrict__ ir,
                                                   float* __restrict__ out)
{
    __shared__ float As[16][128];   // As[k][m] = w_proj[m0+m, k0+k]
    __shared__ float Bs[16][128];   // Bs[k][n] = g_attn[b, k0+k, n0+n]

    const int b  = blockIdx.z;
    const int n0 = blockIdx.x * 128;
    const int m0 = blockIdx.y * 128;   // output channel tile base
    const int tid = threadIdx.x;
    const int tm = (tid >> 4) * 8;
    const int tn = (tid & 15) * 8;

    const float* ab = g_attn + (size_t)b * 256 * NPIX;

    float acc[8][8];
    #pragma unroll
    for (int i = 0; i < 8; i++)
        #pragma unroll
        for (int j = 0; j < 8; j++) acc[i][j] = 0.f;

    for (int k0 = 0; k0 < 256; k0 += 16) {
        #pragma unroll
        for (int t = 0; t < 2; t++) {
            int idx = tid * 2 + t;
            int row = idx >> 2;
            int col = (idx & 3) * 4;
            float4 v = *(const float4*)(w + (size_t)(m0 + row) * 256 + k0 + col);
            As[col + 0][row] = v.x;
            As[col + 1][row] = v.y;
            As[col + 2][row] = v.z;
            As[col + 3][row] = v.w;
        }
        #pragma unroll
        for (int t = 0; t < 2; t++) {
            int idx = tid * 2 + t;
            int kr = idx >> 5;
            int nc = (idx & 31) * 4;
            *(float4*)&Bs[kr][nc] =
                *(const float4*)(ab + (size_t)(k0 + kr) * NPIX + n0 + nc);
        }
        __syncthreads();

        #pragma unroll
        for (int kk = 0; kk < 16; kk++) {
            float4 a0 = *(const float4*)&As[kk][tm];
            float4 a1 = *(const float4*)&As[kk][tm + 4];
            float4 b0 = *(const float4*)&Bs[kk][tn];
            float4 b1 = *(const float4*)&Bs[kk][tn + 4];
            float a[8] = {a0.x, a0.y, a0.z, a0.w, a1.x, a1.y, a1.z, a1.w};
            float bb[8] = {b0.x, b0.y, b0.z, b0.w, b1.x, b1.y, b1.z, b1.w};
            #pragma unroll
            for (int i = 0; i < 8; i++)
                #pragma unroll
                for (int j = 0; j < 8; j++)
                    acc[i][j] = fmaf(a[i], bb[j], acc[i][j]);
        }
        __syncthreads();
    }

    // Epilogue: bias + residual, write [b, n, o] (o contiguous)
    float bp[8];
    #pragma unroll
    for (int i = 0; i < 8; i++) bp[i] = bias[m0 + tm + i];

    // Residual base: channel tile m0 selects rgb (m0==0) or ir (m0==128)
    const float* resb = ((m0 == 0) ? rgb : ir) + (size_t)b * 128 * NPIX;

    #pragma unroll
    for (int j = 0; j < 8; j++) {
        int n = n0 + tn + j;
        float v[8];
        #pragma unroll
        for (int i = 0; i < 8; i++) {
            float res = resb[(size_t)(tm + i) * NPIX + n];
            v[i] = acc[i][j] + bp[i] + res;
        }
        float* dst = out + ((size_t)(b * NPIX + n)) * 256 + m0 + tm;
        *(float4*)(dst)     = make_float4(v[0], v[1], v[2], v[3]);
        *(float4*)(dst + 4) = make_float4(v[4], v[5], v[6], v[7]);
    }
}

// ---------------------------------------------------------------------------
extern "C" void kernel_launch(void* const* d_in, const int* in_sizes, int n_in,
                              void* d_out, int out_size)
{
    const float* rgb    = (const float*)d_in[0];
    const float* ir     = (const float*)d_in[1];
    const float* w_qkv  = (const float*)d_in[2];
    const float* w_proj = (const float*)d_in[3];
    const float* b_proj = (const float*)d_in[4];
    float* out = (float*)d_out;

    qkv_gemm<<<dim3(50, 6, 4), 256>>>(rgb, ir, w_qkv);
    attn_kernel<<<dim3(25, 8, 4), 256>>>();
    proj_kernel<<<dim3(50, 2, 4), 256>>>(w_proj, b_proj, rgb, ir, out);
}